// round 17
// baseline (speedup 1.0000x reference)
#include <cuda_runtime.h>
#include <stdint.h>

#define NCOL     4096
#define TPB      256
#define KSEL     64
#define TGUESS   1.9f      // prefilter guess; exact fallback if it fails
#define BSCALE   512.0f    // bucket scale: bin = min(1023, (int)((fv-TGUESS)*BSCALE))
#define NBIN     1024
#define CAP      768       // per-row candidate capacity (expected ~118)
#define SMALLCAP 64        // boundary-bin brute-force bound
#define NWORD    128       // 4096 elements / 32 bits

// float -> order-preserving uint32 (fallback path only)
__device__ __forceinline__ uint32_t f2k(float f) {
    uint32_t u = __float_as_uint(f);
    return u ^ (uint32_t)((((int32_t)u) >> 31) | (int32_t)0x80000000);
}
__device__ __forceinline__ float k2f(uint32_t k) {
    uint32_t u = (k & 0x80000000u) ? (k ^ 0x80000000u) : ~k;
    return __uint_as_float(u);
}

// inclusive block scan over TPB=256 uint32 values (fallback only). wsum: shared[8].
__device__ __forceinline__ uint32_t block_scan_inc(uint32_t val, uint32_t* wsum, int t) {
    __syncthreads();
    int lane = t & 31, w = t >> 5;
#pragma unroll
    for (int off = 1; off < 32; off <<= 1) {
        uint32_t n = __shfl_up_sync(0xffffffffu, val, off);
        if (lane >= off) val += n;
    }
    if (lane == 31) wsum[w] = val;
    __syncthreads();
    if (w == 0) {
        uint32_t s = (lane < 8) ? wsum[lane] : 0u;
#pragma unroll
        for (int off = 1; off < 8; off <<= 1) {
            uint32_t n = __shfl_up_sync(0xffffffffu, s, off);
            if (lane >= off) s += n;
        }
        if (lane < 8) wsum[lane] = s;
    }
    __syncthreads();
    uint32_t base = (w > 0) ? wsum[w - 1] : 0u;
    return val + base;
}

__device__ __forceinline__ int bucket_of(float fv) {
    int b = (int)((fv - TGUESS) * BSCALE);
    return (b > NBIN - 1) ? (NBIN - 1) : b;     // fv > TGUESS ensures b >= 0
}

__device__ __forceinline__ uint64_t pack_cand(float fv, uint32_t col) {
    // strict total order == "larger value first, then lower column" (top_k tie rule)
    return ((uint64_t)__float_as_uint(fv) << 12) | (uint64_t)(4095u - col);
}

__global__ __launch_bounds__(TPB, 8) void topk_mask_kernel(const float* __restrict__ x,
                                                           float* __restrict__ out) {
    __shared__ uint64_t cand[2][CAP];         // 12 KB packed candidates (2 rows)
    __shared__ uint32_t hist[2][NBIN];        // 8 KB bucket histograms
    __shared__ uint32_t psum[2][256];         // 2 KB 4-bin partial sums
    __shared__ uint32_t bitmap[2][NWORD];     // presence ballots
    __shared__ uint64_t brute[2][SMALLCAP];   // boundary-bin gather buffers
    __shared__ uint32_t wsum[8];
    __shared__ uint32_t s_pos[2], s_bin[2], s_above[2], s_h[2], s_cnt2[2], s_ok[2];
    __shared__ uint64_t s_key[2];
    __shared__ uint32_t keep_bm[NCOL / 32];   // fallback tie path only
    __shared__ uint32_t f_bin, f_above, f_h, f_pos;

    const int t    = threadIdx.x;
    const int lane = t & 31;
    const int w    = t >> 5;
    const size_t offA = (size_t)blockIdx.x * (2 * NCOL);

    if (t < 2) { s_pos[t] = 0; s_cnt2[t] = 0; s_h[t] = 0xFFFFFFFFu; s_ok[t] = 0; }
    ((uint4*)hist)[t]       = make_uint4(0, 0, 0, 0);   // zero 2048 bins
    ((uint4*)hist)[t + TPB] = make_uint4(0, 0, 0, 0);
    // ordering provided by the post-phase-1 barrier (phase 1 touches neither)

    // ---- phase 1: both rows, sequential (regs bounded), ballots only ----
#pragma unroll 1
    for (int r = 0; r < 2; r++) {
        const size_t roff = offA + (size_t)r * NCOL;
        const float4* __restrict__ xr = (const float4*)(x + roff);
        float4* __restrict__ outr     = (float4*)(out + roff);
        float4 qq[4];
#pragma unroll
        for (int v = 0; v < 4; v++) qq[v] = xr[v * TPB + t];
#pragma unroll
        for (int v = 0; v < 4; v++) {
            float4 qv = qq[v];
            bool p0 = (qv.x > TGUESS), p1 = (qv.y > TGUESS);
            bool p2 = (qv.z > TGUESS), p3 = (qv.w > TGUESS);
            float4 o;
            o.x = p0 ? qv.x : 0.0f;
            o.y = p1 ? qv.y : 0.0f;
            o.z = p2 ? qv.z : 0.0f;
            o.w = p3 ? qv.w : 0.0f;
            outr[v * TPB + t] = o;
            unsigned b0 = __ballot_sync(0xffffffffu, p0);
            unsigned b1 = __ballot_sync(0xffffffffu, p1);
            unsigned b2 = __ballot_sync(0xffffffffu, p2);
            unsigned b3 = __ballot_sync(0xffffffffu, p3);
            if (lane == 0)
                ((uint4*)bitmap[r])[v * 8 + w] = make_uint4(b0, b1, b2, b3);
        }
    }
    __syncthreads();

    // ---- phase 2a: reconstruct + compact; half-block per row (word i = v*32+w*4+j) ----
    {
        const int r = t >> 7;
        const int i = t & 127;
        const size_t roff = offA + (size_t)r * NCOL;
        uint32_t m = bitmap[r][i];
        if (m) {
            const uint32_t vv = (uint32_t)(i >> 5);
            const uint32_t ww = (uint32_t)((i >> 2) & 7);
            const uint32_t jj = (uint32_t)(i & 3);
            uint32_t n = (uint32_t)__popc(m);
            uint32_t base = atomicAdd(&s_pos[r], n);
            while (m) {
                int l = __ffs(m) - 1;
                m &= m - 1;
                uint32_t col = (vv * 256u + ww * 32u + (uint32_t)l) * 4u + jj;
                float fv = x[roff + col];             // L2-resident (just read)
                if (base < CAP) cand[r][base] = pack_cand(fv, col);
                base++;
                atomicAdd(&hist[r][bucket_of(fv)], 1u);
            }
        }
    }
    __syncthreads();
    const uint32_t Cr[2]  = { s_pos[0], s_pos[1] };
    const bool   fastr[2] = { Cr[0] >= KSEL && Cr[0] <= CAP,
                              Cr[1] >= KSEL && Cr[1] <= CAP };

    // ---- phase 2b: partial sums for both rows, then warp 0 / warp 1 suffix scans ----
    {
        uint4 a = ((const uint4*)hist[0])[t];
        psum[0][t] = a.x + a.y + a.z + a.w;
        uint4 b = ((const uint4*)hist[1])[t];
        psum[1][t] = b.x + b.y + b.z + b.w;
    }
    __syncthreads();
    if (w < 2 && fastr[w]) {                           // warp-uniform branch
        const int r = w;
        const int sb = 31 - lane;                      // lane owns superbin sb (desc)
        uint4 a = ((const uint4*)psum[r])[2 * sb];
        uint4 b = ((const uint4*)psum[r])[2 * sb + 1];
        uint32_t s8 = a.x + a.y + a.z + a.w + b.x + b.y + b.z + b.w;
        uint32_t S = s8;
#pragma unroll
        for (int off = 1; off < 32; off <<= 1) {
            uint32_t n = __shfl_up_sync(0xffffffffu, S, off);
            if (lane >= off) S += n;
        }
        if (S >= KSEL && (S - s8) < KSEL) {            // boundary superbin: this lane
            uint32_t run = S - s8;
            for (int g = 7; g >= 0; g--) {
                uint32_t pv = psum[r][8 * sb + g];
                if (run + pv >= KSEL) {
                    for (int bb = 4 * (8 * sb + g) + 3;; bb--) {
                        uint32_t hv = hist[r][bb];
                        if (run + hv >= KSEL) { s_bin[r] = (uint32_t)bb; s_above[r] = run; s_h[r] = hv; break; }
                        run += hv;
                    }
                    break;
                }
                run += pv;
            }
        }
    }
    __syncthreads();

    // ---- gather: half-block per row ----
    {
        const int r = t >> 7;
        if (fastr[r] && s_h[r] <= SMALLCAP) {
            const uint32_t target = s_bin[r];
            for (uint32_t i = (uint32_t)(t & 127); i < Cr[r]; i += 128) {
                uint64_t p = cand[r][i];
                if ((uint32_t)bucket_of(__uint_as_float((uint32_t)(p >> 12))) == target) {
                    uint32_t q = atomicAdd(&s_cnt2[r], 1u);
                    brute[r][q] = p;
                }
            }
        }
    }
    __syncthreads();
    // ---- brute: warp 0 row 0, warp 1 row 1 (packed keys all distinct) ----
    if (w < 2 && fastr[w] && s_h[w] <= SMALLCAP) {
        const int r = w;
        const uint32_t kth2 = KSEL - s_above[r];       // rank within boundary bin
        uint32_t n = s_cnt2[r];                        // == s_h[r]
        for (uint32_t i = (uint32_t)lane; i < n; i += 32) {
            uint64_t e = brute[r][i];
            uint32_t gt = 0;
            for (uint32_t j = 0; j < n; j++) gt += (brute[r][j] > e) ? 1u : 0u;
            if (gt == kth2 - 1) { s_key[r] = e; s_ok[r] = 1; }
        }
    }
    __syncthreads();

    // ---- phase 3: sparse fix-up, half-block per row ----
    {
        const int r = t >> 7;
        if (s_ok[r]) {
            const size_t roff = offA + (size_t)r * NCOL;
            const uint64_t key = s_key[r];
            for (uint32_t i = (uint32_t)(t & 127); i < Cr[r]; i += 128) {
                uint64_t p = cand[r][i];
                if (p < key)
                    out[roff + (4095u - (uint32_t)(p & 0xFFFu))] = 0.0f;
            }
        }
    }
    if (s_ok[0] && s_ok[1]) return;                    // uniform (shared flags)
    __syncthreads();                                   // protect cand/hist reuse below

    // ============ fallback: exact full-row select + full rewrite (rare) ============
#pragma unroll 1
    for (int r = 0; r < 2; r++) {
        if (s_ok[r]) continue;                         // uniform
        const size_t roff = offA + (size_t)r * NCOL;
        uint32_t* fhist = hist[0];
        uint32_t prefix = 0, mmask = 0, kth = KSEL, total_eq = 0;
#pragma unroll 1
        for (int pass = 0; pass < 4; pass++) {
            const int shift = 24 - 8 * pass;
            fhist[t] = 0;
            __syncthreads();
            for (int i = t; i < NCOL; i += TPB) {
                uint32_t kk = f2k(x[roff + i]);
                if ((kk & mmask) == prefix) {
                    uint32_t bin = (kk >> shift) & 0xFFu;
                    unsigned act = __activemask();
                    unsigned grp = __match_any_sync(act, bin);
                    if ((grp & ((1u << lane) - 1u)) == 0u)
                        atomicAdd(&fhist[bin], (uint32_t)__popc(grp));
                }
            }
            __syncthreads();
            uint32_t hh = fhist[255 - t];
            uint32_t S = block_scan_inc(hh, wsum, t);
            if (S >= kth && (S - hh) < kth) {
                f_bin = (uint32_t)(255 - t); f_above = S - hh; f_h = hh;
            }
            __syncthreads();
            prefix |= (f_bin << shift);
            mmask  |= (0xFFu << shift);
            kth    -= f_above;
            total_eq = f_h;
            __syncthreads();
        }
        const uint32_t need = kth;
        const float Tf = k2f(prefix);
        const bool tie_rank = (total_eq > need);
        const float4* __restrict__ xr = (const float4*)(x + roff);
        float4* __restrict__ outr     = (float4*)(out + roff);

        if (tie_rank) {
            uint16_t* tiebuf = (uint16_t*)cand;        // 12 KB >= 4096 u16
            if (t == 0) f_pos = 0;
            for (int i = t; i < NCOL / 32; i += TPB) keep_bm[i] = 0;
            __syncthreads();
            for (int i = t; i < NCOL; i += TPB) {
                if (x[roff + i] == Tf) {
                    uint32_t p = atomicAdd(&f_pos, 1u);
                    tiebuf[p] = (uint16_t)i;
                }
            }
            __syncthreads();
            uint32_t total = f_pos;
            for (uint32_t i = t; i < total; i += TPB) {
                uint32_t ci = tiebuf[i], rr = 0;
                for (uint32_t j = 0; j < total; j++) rr += (tiebuf[j] < ci) ? 1u : 0u;
                if (rr < need) atomicOr(&keep_bm[ci >> 5], 1u << (ci & 31));
            }
            __syncthreads();
#pragma unroll
            for (int v = 0; v < 4; v++) {
                float4 q = xr[v * TPB + t];
                float4 o;
                float* ip = (float*)&q;
                float* op = (float*)&o;
#pragma unroll
                for (int j = 0; j < 4; j++) {
                    float fv = ip[j];
                    float val = 0.0f;
                    if (fv > Tf) val = fv;
                    else if (fv == Tf) {
                        uint32_t col = (uint32_t)(v * TPB + t) * 4u + (uint32_t)j;
                        if ((keep_bm[col >> 5] >> (col & 31)) & 1u) val = fv;
                    }
                    op[j] = val;
                }
                outr[v * TPB + t] = o;
            }
        } else {
#pragma unroll
            for (int v = 0; v < 4; v++) {
                float4 q = xr[v * TPB + t];
                float4 o;
                o.x = (q.x >= Tf) ? q.x : 0.0f;
                o.y = (q.y >= Tf) ? q.y : 0.0f;
                o.z = (q.z >= Tf) ? q.z : 0.0f;
                o.w = (q.w >= Tf) ? q.w : 0.0f;
                outr[v * TPB + t] = o;
            }
        }
        __syncthreads();                               // protect shared reuse across rows
    }
}

extern "C" void kernel_launch(void* const* d_in, const int* in_sizes, int n_in,
                              void* d_out, int out_size) {
    const float* x = (const float*)d_in[0];
    float* out = (float*)d_out;
    int rows = in_sizes[0] / NCOL;
    topk_mask_kernel<<<rows / 2, TPB>>>(x, out);
}